// round 3
// baseline (speedup 1.0000x reference)
#include <cuda_runtime.h>

// ---------------- static scratch (no allocation allowed) ----------------
#define MAXN 100000
#define MAXE 1600000

__device__ __align__(16) int   g_deg [MAXN];   // in-degree incl. self-loop
__device__ __align__(16) float g_dinv[MAXN];
__device__ __align__(16) int   g_off [MAXN];   // CSR start per dst node
__device__ __align__(16) int   g_pos [MAXN];   // scatter cursor
__device__ __align__(16) int   g_srci[MAXE];   // edge src
__device__ __align__(16) int   g_dsti[MAXE];   // edge dst
__device__ __align__(16) int   g_csrc[MAXE];   // CSR: src per slot
__device__ __align__(16) float g_cw  [MAXE];   // CSR: weight per slot
__device__ int g_total;
__device__ __align__(16) float g_h1  [MAXN * 64];  // x @ W1
__device__ __align__(16) float g_a1  [MAXN * 64];  // layer-1 aggregated (+b1)
__device__ __align__(16) float g_h2  [MAXN * 64];  // bn(relu(a1)) @ W2
__device__ __align__(16) float g_stats[128];       // [0:64) sum, [64:128) sumsq
__device__ __align__(16) float g_scale[64];
__device__ __align__(16) float g_shift[64];

// ---------------- prep ----------------
__global__ void k_clear(int n) {
    int i = blockIdx.x * blockDim.x + threadIdx.x;
    if (i < n) g_deg[i] = 1;                      // self-loop
    if (blockIdx.x == 0) {
        if (threadIdx.x < 128) g_stats[threadIdx.x] = 0.f;
        if (threadIdx.x == 0)  g_total = 0;
    }
}

// edge_index is int32 on the device side (harness converts int64 -> int32).
__global__ void k_edges(const int* __restrict__ ei, int E, int n) {
    int e = blockIdx.x * blockDim.x + threadIdx.x;
    if (e >= E) return;
    int s = ei[e];
    int d = ei[E + e];
    if ((unsigned)s >= (unsigned)n) s = 0;   // defensive; never taken when dtype is right
    if ((unsigned)d >= (unsigned)n) d = 0;
    g_srci[e] = s;
    g_dsti[e] = d;
    atomicAdd(&g_deg[d], 1);
}

__global__ void k_dinv(int n) {
    int i = blockIdx.x * blockDim.x + threadIdx.x;
    if (i < n) g_dinv[i] = rsqrtf((float)g_deg[i]);
}

// per-block inclusive scan + atomic block base -> contiguous CSR slots per node
__global__ __launch_bounds__(256) void k_off(int n) {
    __shared__ int sh[256];
    __shared__ int base;
    int tid = threadIdx.x;
    int i = blockIdx.x * 256 + tid;
    int v = (i < n) ? (g_deg[i] - 1) : 0;        // in-edges excl self-loop
    sh[tid] = v;
    __syncthreads();
    #pragma unroll
    for (int o = 1; o < 256; o <<= 1) {
        int t = (tid >= o) ? sh[tid - o] : 0;
        __syncthreads();
        sh[tid] += t;
        __syncthreads();
    }
    if (tid == 255) base = atomicAdd(&g_total, sh[255]);
    __syncthreads();
    if (i < n) {
        int start = base + sh[tid] - v;          // exclusive
        g_off[i] = start;
        g_pos[i] = start;
    }
}

__global__ void k_scatter(int E) {
    int e = blockIdx.x * blockDim.x + threadIdx.x;
    if (e >= E) return;
    int s = g_srci[e];
    int d = g_dsti[e];
    int p = atomicAdd(&g_pos[d], 1);
    if (p < MAXE) {
        g_csrc[p] = s;
        g_cw[p]   = g_dinv[s] * g_dinv[d];
    }
}

// ---------------- GEMM: [n,K] @ [K,64] -> [n,64] ----------------
// LAYER 1: X = x (param), K=128, out = g_h1
// LAYER 2: X = g_a1 with fused BN+ReLU, K=64, out = g_h2
template <int LAYER>
__global__ __launch_bounds__(256)
void gemm64(const float* __restrict__ xin, const float* __restrict__ Wm, int n) {
    constexpr int K = (LAYER == 1) ? 128 : 64;
    const float* X = (LAYER == 1) ? xin : (const float*)g_a1;
    float* H = (LAYER == 1) ? g_h1 : g_h2;

    __shared__ __align__(16) float sX[64 * 68];
    __shared__ __align__(16) float sW[64 * 64];

    int t  = threadIdx.x;
    int tx = t & 15;
    int ty = t >> 4;
    int c0 = tx * 4;
    int r0 = ty * 4;
    int rowBase = blockIdx.x * 64;

    float acc[4][4] = {};

    for (int k0 = 0; k0 < K; k0 += 64) {
        int kq = tx;
        int rr = ty;
        #pragma unroll
        for (int j = 0; j < 4; j++) {
            int kk = rr + j * 16;
            float4 wv = *(const float4*)&Wm[(long)(k0 + kk) * 64 + kq * 4];
            *(float4*)&sW[kk * 64 + kq * 4] = wv;
        }
        #pragma unroll
        for (int j = 0; j < 4; j++) {
            int row  = rr + j * 16;
            int grow = rowBase + row;
            float4 xv = make_float4(0.f, 0.f, 0.f, 0.f);
            if (grow < n) {
                xv = *(const float4*)&X[(long)grow * K + k0 + kq * 4];
                if (LAYER == 2) {
                    float4 sc = *(const float4*)&g_scale[kq * 4];
                    float4 sf = *(const float4*)&g_shift[kq * 4];
                    xv.x = fmaxf(fmaf(xv.x, sc.x, sf.x), 0.f);
                    xv.y = fmaxf(fmaf(xv.y, sc.y, sf.y), 0.f);
                    xv.z = fmaxf(fmaf(xv.z, sc.z, sf.z), 0.f);
                    xv.w = fmaxf(fmaf(xv.w, sc.w, sf.w), 0.f);
                }
            }
            *(float4*)&sX[row * 68 + kq * 4] = xv;
        }
        __syncthreads();

        #pragma unroll
        for (int kk = 0; kk < 64; kk++) {
            float4 wv = *(const float4*)&sW[kk * 64 + c0];
            #pragma unroll
            for (int i = 0; i < 4; i++) {
                float a = sX[(r0 + i) * 68 + kk];
                acc[i][0] = fmaf(a, wv.x, acc[i][0]);
                acc[i][1] = fmaf(a, wv.y, acc[i][1]);
                acc[i][2] = fmaf(a, wv.z, acc[i][2]);
                acc[i][3] = fmaf(a, wv.w, acc[i][3]);
            }
        }
        __syncthreads();
    }

    #pragma unroll
    for (int i = 0; i < 4; i++) {
        int grow = rowBase + r0 + i;
        if (grow < n)
            *(float4*)&H[(long)grow * 64 + c0] =
                make_float4(acc[i][0], acc[i][1], acc[i][2], acc[i][3]);
    }
}

// ---------------- aggregation (pure gather, CSR by dst) ----------------
// out[i] = dinv[i]^2 * H[i] + b + sum_{j in in(i)} w_j * H[src_j]
// 16 threads per node; each owns one float4 lane of the 64-wide row.
template <int LAYER>
__global__ __launch_bounds__(256)
void agg(float* __restrict__ outp, const float* __restrict__ b, int n) {
    const float* H = (LAYER == 1) ? g_h1 : g_h2;
    float* O = (LAYER == 1) ? g_a1 : outp;

    int tid   = threadIdx.x;
    int local = tid >> 4;                 // node within block (0..15)
    int q     = tid & 15;                 // float4 lane
    int i = blockIdx.x * 16 + local;
    if (i >= n) return;

    float d  = g_dinv[i];
    float d2 = d * d;
    float4 acc = *(const float4*)&H[(long)i * 64 + q * 4];
    float4 bb  = *(const float4*)&b[q * 4];
    acc.x = fmaf(acc.x, d2, bb.x);
    acc.y = fmaf(acc.y, d2, bb.y);
    acc.z = fmaf(acc.z, d2, bb.z);
    acc.w = fmaf(acc.w, d2, bb.w);

    int start = g_off[i];
    int end   = start + (g_deg[i] - 1);

    int j = start;
    for (; j + 1 < end; j += 2) {
        int   s0 = g_csrc[j],     s1 = g_csrc[j + 1];
        float w0 = g_cw[j],       w1 = g_cw[j + 1];
        float4 v0 = *(const float4*)&H[(long)s0 * 64 + q * 4];
        float4 v1 = *(const float4*)&H[(long)s1 * 64 + q * 4];
        acc.x = fmaf(w0, v0.x, acc.x); acc.y = fmaf(w0, v0.y, acc.y);
        acc.z = fmaf(w0, v0.z, acc.z); acc.w = fmaf(w0, v0.w, acc.w);
        acc.x = fmaf(w1, v1.x, acc.x); acc.y = fmaf(w1, v1.y, acc.y);
        acc.z = fmaf(w1, v1.z, acc.z); acc.w = fmaf(w1, v1.w, acc.w);
    }
    if (j < end) {
        int   s0 = g_csrc[j];
        float w0 = g_cw[j];
        float4 v0 = *(const float4*)&H[(long)s0 * 64 + q * 4];
        acc.x = fmaf(w0, v0.x, acc.x); acc.y = fmaf(w0, v0.y, acc.y);
        acc.z = fmaf(w0, v0.z, acc.z); acc.w = fmaf(w0, v0.w, acc.w);
    }

    *(float4*)&O[(long)i * 64 + q * 4] = acc;
}

// ---------------- batchnorm ----------------
__global__ __launch_bounds__(256) void bn_stats(int n) {
    const float* A = g_a1;
    int c = threadIdx.x & 63;
    int g = threadIdx.x >> 6;
    float s = 0.f, s2 = 0.f;
    for (int r = blockIdx.x * 4 + g; r < n; r += gridDim.x * 4) {
        float v = A[(long)r * 64 + c];
        s  += v;
        s2 += v * v;
    }
    __shared__ float sh[2][4][64];
    sh[0][g][c] = s;
    sh[1][g][c] = s2;
    __syncthreads();
    if (g == 0) {
        s  = sh[0][0][c] + sh[0][1][c] + sh[0][2][c] + sh[0][3][c];
        s2 = sh[1][0][c] + sh[1][1][c] + sh[1][2][c] + sh[1][3][c];
        atomicAdd(&g_stats[c], s);
        atomicAdd(&g_stats[64 + c], s2);
    }
}

__global__ void bn_final(const float* __restrict__ gamma,
                         const float* __restrict__ beta, int n) {
    int c = threadIdx.x;
    if (c >= 64) return;
    float inv_n = 1.f / (float)n;
    float mean = g_stats[c] * inv_n;
    float var  = g_stats[64 + c] * inv_n - mean * mean;
    float rs   = rsqrtf(var + 1e-5f);
    float sc   = rs * gamma[c];
    g_scale[c] = sc;
    g_shift[c] = fmaf(-mean, sc, beta[c]);
}

// ---------------- launch ----------------
extern "C" void kernel_launch(void* const* d_in, const int* in_sizes, int n_in,
                              void* d_out, int out_size) {
    const float* x     = (const float*)d_in[0];
    const int*   ei    = (const int*)d_in[1];     // int64 downcast to int32 by harness
    const float* W1    = (const float*)d_in[2];
    const float* b1    = (const float*)d_in[3];
    const float* W2    = (const float*)d_in[4];
    const float* b2    = (const float*)d_in[5];
    const float* gamma = (const float*)d_in[6];
    const float* beta  = (const float*)d_in[7];
    float*       out   = (float*)d_out;

    int n = in_sizes[0] / 128;
    int E = in_sizes[1] / 2;

    const int T = 256;
    int nb = (n + T - 1) / T;
    int eb = (E + T - 1) / T;
    int gemm_blocks = (n + 63) / 64;
    int agg_blocks  = (n + 15) / 16;

    // ---- CSR build ----
    k_clear   <<<nb, T>>>(n);
    k_edges   <<<eb, T>>>(ei, E, n);
    k_dinv    <<<nb, T>>>(n);
    k_off     <<<nb, T>>>(n);
    k_scatter <<<eb, T>>>(E);

    // ---- layer 1 ----
    gemm64<1> <<<gemm_blocks, T>>>(x, W1, n);
    agg<1>    <<<agg_blocks, T>>>(nullptr, b1, n);

    // ---- batchnorm fold ----
    bn_stats  <<<512, T>>>(n);
    bn_final  <<<1, 64>>>(gamma, beta, n);

    // ---- layer 2 ----
    gemm64<2> <<<gemm_blocks, T>>>(x, W2, n);
    agg<2>    <<<agg_blocks, T>>>(out, b2, n);
}

// round 4
// speedup vs baseline: 1.0345x; 1.0345x over previous
#include <cuda_runtime.h>

// ---------------- static scratch (no allocation allowed) ----------------
#define MAXN 100000
#define MAXE 1600000

__device__ __align__(16) int   g_deg [MAXN];   // in-degree incl. self-loop
__device__ __align__(16) float g_dinv[MAXN];
__device__ __align__(16) int   g_off [MAXN];   // CSR start per dst node
__device__ __align__(16) int   g_pos [MAXN];   // scatter cursor
__device__ __align__(16) int   g_csrc[MAXE];   // CSR: src per slot
__device__ __align__(16) float g_cw  [MAXE];   // CSR: weight per slot
__device__ int g_total;
__device__ __align__(16) float g_h1  [MAXN * 64];  // x @ W1
__device__ __align__(16) float g_a1  [MAXN * 64];  // layer-1 aggregated (+b1)
__device__ __align__(16) float g_h2  [MAXN * 64];  // bn(relu(a1)) @ W2
__device__ __align__(16) float g_stats[128];       // [0:64) sum, [64:128) sumsq
__device__ __align__(16) float g_scale[64];
__device__ __align__(16) float g_shift[64];

// packed fp32x2 FMA (sm_100+): d = a * b + d, elementwise on packed pairs
__device__ __forceinline__ void ffma2(unsigned long long& d,
                                      unsigned long long a,
                                      unsigned long long b) {
    asm("fma.rn.f32x2 %0, %1, %2, %3;" : "=l"(d) : "l"(a), "l"(b), "l"(d));
}
__device__ __forceinline__ unsigned long long pack_dup(float a) {
    unsigned long long r;
    asm("mov.b64 %0, {%1, %1};" : "=l"(r) : "f"(a));
    return r;
}
__device__ __forceinline__ float2 unpack2(unsigned long long v) {
    float2 r;
    asm("mov.b64 {%0, %1}, %2;" : "=f"(r.x), "=f"(r.y) : "l"(v));
    return r;
}

// ---------------- prep ----------------
__global__ void k_clear(int n) {
    int i = blockIdx.x * blockDim.x + threadIdx.x;
    if (i < n) g_deg[i] = 1;                      // self-loop
    if (blockIdx.x == 0) {
        if (threadIdx.x < 128) g_stats[threadIdx.x] = 0.f;
        if (threadIdx.x == 0)  g_total = 0;
    }
}

// edge_index arrives as int32 on device (harness downcasts int64)
__global__ void k_edges(const int* __restrict__ ei, int E, int n) {
    int e = blockIdx.x * blockDim.x + threadIdx.x;
    if (e >= E) return;
    int d = ei[E + e];
    if ((unsigned)d >= (unsigned)n) d = 0;
    atomicAdd(&g_deg[d], 1);
}

// per-block scan + atomic base -> CSR offsets; also dinv
__global__ __launch_bounds__(256) void k_off(int n) {
    __shared__ int sh[256];
    __shared__ int base;
    int tid = threadIdx.x;
    int i = blockIdx.x * 256 + tid;
    int deg = (i < n) ? g_deg[i] : 1;
    int v = deg - 1;                              // in-edges excl self-loop
    sh[tid] = v;
    __syncthreads();
    #pragma unroll
    for (int o = 1; o < 256; o <<= 1) {
        int t = (tid >= o) ? sh[tid - o] : 0;
        __syncthreads();
        sh[tid] += t;
        __syncthreads();
    }
    if (tid == 255) base = atomicAdd(&g_total, sh[255]);
    __syncthreads();
    if (i < n) {
        int start = base + sh[tid] - v;           // exclusive
        g_off[i]  = start;
        g_pos[i]  = start;
        g_dinv[i] = rsqrtf((float)deg);
    }
}

__global__ void k_scatter(const int* __restrict__ ei, int E, int n) {
    int e = blockIdx.x * blockDim.x + threadIdx.x;
    if (e >= E) return;
    int s = ei[e];
    int d = ei[E + e];
    if ((unsigned)s >= (unsigned)n) s = 0;
    if ((unsigned)d >= (unsigned)n) d = 0;
    int p = atomicAdd(&g_pos[d], 1);
    if (p < MAXE) {
        g_csrc[p] = s;
        g_cw[p]   = g_dinv[s] * g_dinv[d];
    }
}

// ---------------- GEMM: [n,K] @ [K,64] -> [n,64], packed f32x2 FMA ----------------
// LAYER 1: X = x, K=128, out = g_h1
// LAYER 2: X = g_a1 with fused BN+ReLU, K=64, out = g_h2
template <int LAYER>
__global__ __launch_bounds__(256)
void gemm64(const float* __restrict__ xin, const float* __restrict__ Wm, int n) {
    constexpr int K = (LAYER == 1) ? 128 : 64;
    const float* X = (LAYER == 1) ? xin : (const float*)g_a1;
    float* H = (LAYER == 1) ? g_h1 : g_h2;

    __shared__ __align__(16) float sX[64 * 68];
    __shared__ __align__(16) float sW[64 * 64];

    int t  = threadIdx.x;
    int tx = t & 15;
    int ty = t >> 4;
    int c0 = tx * 4;
    int r0 = ty * 4;
    int rowBase = blockIdx.x * 64;

    unsigned long long acc2[4][2] = {};   // 4 rows x (2 packed col-pairs)

    for (int k0 = 0; k0 < K; k0 += 64) {
        int kq = tx;
        int rr = ty;
        #pragma unroll
        for (int j = 0; j < 4; j++) {
            int kk = rr + j * 16;
            float4 wv = *(const float4*)&Wm[(long)(k0 + kk) * 64 + kq * 4];
            *(float4*)&sW[kk * 64 + kq * 4] = wv;
        }
        #pragma unroll
        for (int j = 0; j < 4; j++) {
            int row  = rr + j * 16;
            int grow = rowBase + row;
            float4 xv = make_float4(0.f, 0.f, 0.f, 0.f);
            if (grow < n) {
                xv = *(const float4*)&X[(long)grow * K + k0 + kq * 4];
                if (LAYER == 2) {
                    float4 sc = *(const float4*)&g_scale[kq * 4];
                    float4 sf = *(const float4*)&g_shift[kq * 4];
                    xv.x = fmaxf(fmaf(xv.x, sc.x, sf.x), 0.f);
                    xv.y = fmaxf(fmaf(xv.y, sc.y, sf.y), 0.f);
                    xv.z = fmaxf(fmaf(xv.z, sc.z, sf.z), 0.f);
                    xv.w = fmaxf(fmaf(xv.w, sc.w, sf.w), 0.f);
                }
            }
            *(float4*)&sX[row * 68 + kq * 4] = xv;
        }
        __syncthreads();

        #pragma unroll
        for (int kk = 0; kk < 64; kk++) {
            // two packed column pairs (bit-reinterpret of 4 consecutive floats)
            ulonglong2 wp = *(const ulonglong2*)&sW[kk * 64 + c0];
            #pragma unroll
            for (int i = 0; i < 4; i++) {
                unsigned long long aa = pack_dup(sX[(r0 + i) * 68 + kk]);
                ffma2(acc2[i][0], aa, wp.x);
                ffma2(acc2[i][1], aa, wp.y);
            }
        }
        __syncthreads();
    }

    #pragma unroll
    for (int i = 0; i < 4; i++) {
        int grow = rowBase + r0 + i;
        if (grow < n) {
            float2 lo = unpack2(acc2[i][0]);
            float2 hi = unpack2(acc2[i][1]);
            *(float4*)&H[(long)grow * 64 + c0] = make_float4(lo.x, lo.y, hi.x, hi.y);
        }
    }
}

// ---------------- aggregation (pure gather, CSR by dst) ----------------
// out[i] = dinv[i]^2 * H[i] + b + sum_j w_j * H[src_j]
// 16 threads per node, one float4 lane each. LAYER 1 fuses BN statistics.
template <int LAYER>
__global__ __launch_bounds__(256)
void agg(float* __restrict__ outp, const float* __restrict__ b, int n) {
    const float* H = (LAYER == 1) ? g_h1 : g_h2;
    float* O = (LAYER == 1) ? g_a1 : outp;

    int tid   = threadIdx.x;
    int local = tid >> 4;
    int q     = tid & 15;
    int i = blockIdx.x * 16 + local;
    bool valid = (i < n);

    float4 acc = make_float4(0.f, 0.f, 0.f, 0.f);
    if (valid) {
        float d  = g_dinv[i];
        float d2 = d * d;
        float4 h  = *(const float4*)&H[(long)i * 64 + q * 4];
        float4 bb = *(const float4*)&b[q * 4];
        acc.x = fmaf(h.x, d2, bb.x);
        acc.y = fmaf(h.y, d2, bb.y);
        acc.z = fmaf(h.z, d2, bb.z);
        acc.w = fmaf(h.w, d2, bb.w);

        int start = g_off[i];
        int end   = start + (g_deg[i] - 1);
        int j = start;
        for (; j + 1 < end; j += 2) {
            int   s0 = g_csrc[j],     s1 = g_csrc[j + 1];
            float w0 = g_cw[j],       w1 = g_cw[j + 1];
            float4 v0 = *(const float4*)&H[(long)s0 * 64 + q * 4];
            float4 v1 = *(const float4*)&H[(long)s1 * 64 + q * 4];
            acc.x = fmaf(w0, v0.x, acc.x); acc.y = fmaf(w0, v0.y, acc.y);
            acc.z = fmaf(w0, v0.z, acc.z); acc.w = fmaf(w0, v0.w, acc.w);
            acc.x = fmaf(w1, v1.x, acc.x); acc.y = fmaf(w1, v1.y, acc.y);
            acc.z = fmaf(w1, v1.z, acc.z); acc.w = fmaf(w1, v1.w, acc.w);
        }
        if (j < end) {
            int   s0 = g_csrc[j];
            float w0 = g_cw[j];
            float4 v0 = *(const float4*)&H[(long)s0 * 64 + q * 4];
            acc.x = fmaf(w0, v0.x, acc.x); acc.y = fmaf(w0, v0.y, acc.y);
            acc.z = fmaf(w0, v0.z, acc.z); acc.w = fmaf(w0, v0.w, acc.w);
        }

        *(float4*)&O[(long)i * 64 + q * 4] = acc;
    }

    if (LAYER == 1) {
        // fused BN statistics: stage block tile, 64 threads reduce 16 rows
        __shared__ __align__(16) float sv[16][68];
        *(float4*)&sv[local][q * 4] = acc;        // zeros when !valid
        __syncthreads();
        if (tid < 64) {
            float s = 0.f, s2 = 0.f;
            #pragma unroll
            for (int r = 0; r < 16; r++) {
                float v = sv[r][tid];
                s  += v;
                s2 += v * v;
            }
            atomicAdd(&g_stats[tid], s);
            atomicAdd(&g_stats[64 + tid], s2);
        }
    }
}

// ---------------- batchnorm fold ----------------
__global__ void bn_final(const float* __restrict__ gamma,
                         const float* __restrict__ beta, int n) {
    int c = threadIdx.x;
    if (c >= 64) return;
    float inv_n = 1.f / (float)n;
    float mean = g_stats[c] * inv_n;
    float var  = g_stats[64 + c] * inv_n - mean * mean;
    float rs   = rsqrtf(var + 1e-5f);
    float sc   = rs * gamma[c];
    g_scale[c] = sc;
    g_shift[c] = fmaf(-mean, sc, beta[c]);
}

// ---------------- launch ----------------
extern "C" void kernel_launch(void* const* d_in, const int* in_sizes, int n_in,
                              void* d_out, int out_size) {
    const float* x     = (const float*)d_in[0];
    const int*   ei    = (const int*)d_in[1];
    const float* W1    = (const float*)d_in[2];
    const float* b1    = (const float*)d_in[3];
    const float* W2    = (const float*)d_in[4];
    const float* b2    = (const float*)d_in[5];
    const float* gamma = (const float*)d_in[6];
    const float* beta  = (const float*)d_in[7];
    float*       out   = (float*)d_out;

    int n = in_sizes[0] / 128;
    int E = in_sizes[1] / 2;

    const int T = 256;
    int nb = (n + T - 1) / T;
    int eb = (E + T - 1) / T;
    int gemm_blocks = (n + 63) / 64;
    int agg_blocks  = (n + 15) / 16;

    // ---- CSR build ----
    k_clear   <<<nb, T>>>(n);
    k_edges   <<<eb, T>>>(ei, E, n);
    k_off     <<<nb, T>>>(n);
    k_scatter <<<eb, T>>>(ei, E, n);

    // ---- layer 1 (+ fused BN stats) ----
    gemm64<1> <<<gemm_blocks, T>>>(x, W1, n);
    agg<1>    <<<agg_blocks, T>>>(nullptr, b1, n);

    // ---- batchnorm fold ----
    bn_final  <<<1, 64>>>(gamma, beta, n);

    // ---- layer 2 (BN+ReLU fused into GEMM input) ----
    gemm64<2> <<<gemm_blocks, T>>>(x, W2, n);
    agg<2>    <<<agg_blocks, T>>>(out, b2, n);
}

// round 5
// speedup vs baseline: 1.0741x; 1.0382x over previous
#include <cuda_runtime.h>

// ---------------- static scratch (no allocation allowed) ----------------
#define MAXN 100000
#define MAXE 1600000

__device__ __align__(16) int   g_deg [MAXN];   // in-degree incl. self-loop
__device__ __align__(16) float g_dinv[MAXN];
__device__ __align__(16) int   g_off [MAXN];   // CSR start per dst node
__device__ __align__(16) int   g_pos [MAXN];   // scatter cursor
__device__ __align__(16) int   g_csrc[MAXE];   // CSR: src per slot (no weights!)
__device__ int g_total;
__device__ __align__(16) float g_h1  [MAXN * 64];  // dinv * (x @ W1)
__device__ __align__(16) float g_a1  [MAXN * 64];  // layer-1 output (post agg,+b1)
__device__ __align__(16) float g_h2  [MAXN * 64];  // dinv * (bn(relu(a1)) @ W2)
__device__ __align__(16) float g_stats[128];       // [0:64) sum, [64:128) sumsq
__device__ __align__(16) float g_scale[64];
__device__ __align__(16) float g_shift[64];

// packed fp32x2 FMA (sm_100+)
__device__ __forceinline__ void ffma2(unsigned long long& d,
                                      unsigned long long a,
                                      unsigned long long b) {
    asm("fma.rn.f32x2 %0, %1, %2, %3;" : "=l"(d) : "l"(a), "l"(b), "l"(d));
}
__device__ __forceinline__ unsigned long long pack_dup(float a) {
    unsigned long long r;
    asm("mov.b64 %0, {%1, %1};" : "=l"(r) : "f"(a));
    return r;
}
__device__ __forceinline__ float2 unpack2(unsigned long long v) {
    float2 r;
    asm("mov.b64 {%0, %1}, %2;" : "=f"(r.x), "=f"(r.y) : "l"(v));
    return r;
}

// ---------------- prep ----------------
__global__ void k_clear(int n) {
    int i = blockIdx.x * blockDim.x + threadIdx.x;
    if (i < n) g_deg[i] = 1;                      // self-loop
    if (blockIdx.x == 0) {
        if (threadIdx.x < 128) g_stats[threadIdx.x] = 0.f;
        if (threadIdx.x == 0)  g_total = 0;
    }
}

// degree count: 4 edges per thread, vector load of dst
__global__ void k_edges(const int* __restrict__ ei, int E, int n) {
    int e4 = (blockIdx.x * blockDim.x + threadIdx.x) * 4;
    if (e4 >= E) return;
    const int* dstp = ei + E;
    if (e4 + 3 < E) {
        int4 d4 = *(const int4*)&dstp[e4];
        if ((unsigned)d4.x >= (unsigned)n) d4.x = 0;
        if ((unsigned)d4.y >= (unsigned)n) d4.y = 0;
        if ((unsigned)d4.z >= (unsigned)n) d4.z = 0;
        if ((unsigned)d4.w >= (unsigned)n) d4.w = 0;
        atomicAdd(&g_deg[d4.x], 1);
        atomicAdd(&g_deg[d4.y], 1);
        atomicAdd(&g_deg[d4.z], 1);
        atomicAdd(&g_deg[d4.w], 1);
    } else {
        for (int e = e4; e < E; e++) {
            int d = dstp[e];
            if ((unsigned)d >= (unsigned)n) d = 0;
            atomicAdd(&g_deg[d], 1);
        }
    }
}

// per-block scan + atomic base -> CSR offsets; also dinv
__global__ __launch_bounds__(256) void k_off(int n) {
    __shared__ int sh[256];
    __shared__ int base;
    int tid = threadIdx.x;
    int i = blockIdx.x * 256 + tid;
    int deg = (i < n) ? g_deg[i] : 1;
    int v = deg - 1;
    sh[tid] = v;
    __syncthreads();
    #pragma unroll
    for (int o = 1; o < 256; o <<= 1) {
        int t = (tid >= o) ? sh[tid - o] : 0;
        __syncthreads();
        sh[tid] += t;
        __syncthreads();
    }
    if (tid == 255) base = atomicAdd(&g_total, sh[255]);
    __syncthreads();
    if (i < n) {
        int start = base + sh[tid] - v;
        g_off[i]  = start;
        g_pos[i]  = start;
        g_dinv[i] = rsqrtf((float)deg);
    }
}

// scatter src ids only (weights eliminated algebraically)
__global__ void k_scatter(const int* __restrict__ ei, int E, int n) {
    int e = blockIdx.x * blockDim.x + threadIdx.x;
    if (e >= E) return;
    int s = ei[e];
    int d = ei[E + e];
    if ((unsigned)s >= (unsigned)n) s = 0;
    if ((unsigned)d >= (unsigned)n) d = 0;
    int p = atomicAdd(&g_pos[d], 1);
    if (p < MAXE) g_csrc[p] = s;
}

// ---------------- GEMM: [n,K] @ [K,64] -> dinv[row] * result ----------------
// LAYER 1: X = x, K=128, out = g_h1
// LAYER 2: X = g_a1 with fused BN+ReLU, K=64, out = g_h2
template <int LAYER>
__global__ __launch_bounds__(256)
void gemm64(const float* __restrict__ xin, const float* __restrict__ Wm, int n) {
    constexpr int K = (LAYER == 1) ? 128 : 64;
    const float* X = (LAYER == 1) ? xin : (const float*)g_a1;
    float* H = (LAYER == 1) ? g_h1 : g_h2;

    __shared__ __align__(16) float sX[64 * 68];
    __shared__ __align__(16) float sW[64 * 64];

    int t  = threadIdx.x;
    int tx = t & 15;
    int ty = t >> 4;
    int c0 = tx * 4;
    int r0 = ty * 4;
    int rowBase = blockIdx.x * 64;

    unsigned long long acc2[4][2] = {};

    for (int k0 = 0; k0 < K; k0 += 64) {
        int kq = tx;
        int rr = ty;
        #pragma unroll
        for (int j = 0; j < 4; j++) {
            int kk = rr + j * 16;
            float4 wv = *(const float4*)&Wm[(long)(k0 + kk) * 64 + kq * 4];
            *(float4*)&sW[kk * 64 + kq * 4] = wv;
        }
        #pragma unroll
        for (int j = 0; j < 4; j++) {
            int row  = rr + j * 16;
            int grow = rowBase + row;
            float4 xv = make_float4(0.f, 0.f, 0.f, 0.f);
            if (grow < n) {
                xv = *(const float4*)&X[(long)grow * K + k0 + kq * 4];
                if (LAYER == 2) {
                    float4 sc = *(const float4*)&g_scale[kq * 4];
                    float4 sf = *(const float4*)&g_shift[kq * 4];
                    xv.x = fmaxf(fmaf(xv.x, sc.x, sf.x), 0.f);
                    xv.y = fmaxf(fmaf(xv.y, sc.y, sf.y), 0.f);
                    xv.z = fmaxf(fmaf(xv.z, sc.z, sf.z), 0.f);
                    xv.w = fmaxf(fmaf(xv.w, sc.w, sf.w), 0.f);
                }
            }
            *(float4*)&sX[row * 68 + kq * 4] = xv;
        }
        __syncthreads();

        #pragma unroll
        for (int kk = 0; kk < 64; kk++) {
            ulonglong2 wp = *(const ulonglong2*)&sW[kk * 64 + c0];
            #pragma unroll
            for (int i = 0; i < 4; i++) {
                unsigned long long aa = pack_dup(sX[(r0 + i) * 68 + kk]);
                ffma2(acc2[i][0], aa, wp.x);
                ffma2(acc2[i][1], aa, wp.y);
            }
        }
        __syncthreads();
    }

    #pragma unroll
    for (int i = 0; i < 4; i++) {
        int grow = rowBase + r0 + i;
        if (grow < n) {
            float dv = g_dinv[grow];
            float2 lo = unpack2(acc2[i][0]);
            float2 hi = unpack2(acc2[i][1]);
            *(float4*)&H[(long)grow * 64 + c0] =
                make_float4(lo.x * dv, lo.y * dv, hi.x * dv, hi.y * dv);
        }
    }
}

// ---------------- aggregation (pure unweighted gather) ----------------
// out[i] = dinv[i] * (Hs[i] + sum_j Hs[src_j]) + b
// 16 threads per node, one float4 lane each. LAYER 1 fuses BN statistics.
template <int LAYER>
__global__ __launch_bounds__(256)
void agg(float* __restrict__ outp, const float* __restrict__ b, int n) {
    const float* H = (LAYER == 1) ? g_h1 : g_h2;
    float* O = (LAYER == 1) ? g_a1 : outp;

    int tid   = threadIdx.x;
    int local = tid >> 4;
    int q     = tid & 15;
    int i = blockIdx.x * 16 + local;
    bool valid = (i < n);

    float4 out4 = make_float4(0.f, 0.f, 0.f, 0.f);
    if (valid) {
        float4 acc = *(const float4*)&H[(long)i * 64 + q * 4];   // self-loop term

        int start = g_off[i];
        int end   = start + (g_deg[i] - 1);
        int j = start;
        for (; j + 3 < end; j += 4) {
            int s0 = g_csrc[j];
            int s1 = g_csrc[j + 1];
            int s2 = g_csrc[j + 2];
            int s3 = g_csrc[j + 3];
            float4 v0 = *(const float4*)&H[(long)s0 * 64 + q * 4];
            float4 v1 = *(const float4*)&H[(long)s1 * 64 + q * 4];
            float4 v2 = *(const float4*)&H[(long)s2 * 64 + q * 4];
            float4 v3 = *(const float4*)&H[(long)s3 * 64 + q * 4];
            acc.x += v0.x + v1.x; acc.y += v0.y + v1.y;
            acc.z += v0.z + v1.z; acc.w += v0.w + v1.w;
            acc.x += v2.x + v3.x; acc.y += v2.y + v3.y;
            acc.z += v2.z + v3.z; acc.w += v2.w + v3.w;
        }
        for (; j < end; j++) {
            int s0 = g_csrc[j];
            float4 v0 = *(const float4*)&H[(long)s0 * 64 + q * 4];
            acc.x += v0.x; acc.y += v0.y; acc.z += v0.z; acc.w += v0.w;
        }

        float dv = g_dinv[i];
        float4 bb = *(const float4*)&b[q * 4];
        out4.x = fmaf(acc.x, dv, bb.x);
        out4.y = fmaf(acc.y, dv, bb.y);
        out4.z = fmaf(acc.z, dv, bb.z);
        out4.w = fmaf(acc.w, dv, bb.w);

        *(float4*)&O[(long)i * 64 + q * 4] = out4;
    }

    if (LAYER == 1) {
        __shared__ __align__(16) float sv[16][68];
        *(float4*)&sv[local][q * 4] = out4;       // zeros when !valid
        __syncthreads();
        if (tid < 64) {
            float s = 0.f, s2 = 0.f;
            #pragma unroll
            for (int r = 0; r < 16; r++) {
                float v = sv[r][tid];
                s  += v;
                s2 += v * v;
            }
            atomicAdd(&g_stats[tid], s);
            atomicAdd(&g_stats[64 + tid], s2);
        }
    }
}

// ---------------- batchnorm fold ----------------
__global__ void bn_final(const float* __restrict__ gamma,
                         const float* __restrict__ beta, int n) {
    int c = threadIdx.x;
    if (c >= 64) return;
    float inv_n = 1.f / (float)n;
    float mean = g_stats[c] * inv_n;
    float var  = g_stats[64 + c] * inv_n - mean * mean;
    float rs   = rsqrtf(var + 1e-5f);
    float sc   = rs * gamma[c];
    g_scale[c] = sc;
    g_shift[c] = fmaf(-mean, sc, beta[c]);
}

// ---------------- launch ----------------
extern "C" void kernel_launch(void* const* d_in, const int* in_sizes, int n_in,
                              void* d_out, int out_size) {
    const float* x     = (const float*)d_in[0];
    const int*   ei    = (const int*)d_in[1];
    const float* W1    = (const float*)d_in[2];
    const float* b1    = (const float*)d_in[3];
    const float* W2    = (const float*)d_in[4];
    const float* b2    = (const float*)d_in[5];
    const float* gamma = (const float*)d_in[6];
    const float* beta  = (const float*)d_in[7];
    float*       out   = (float*)d_out;

    int n = in_sizes[0] / 128;
    int E = in_sizes[1] / 2;

    const int T = 256;
    int nb  = (n + T - 1) / T;
    int eb  = (E + T - 1) / T;
    int eb4 = (E + T * 4 - 1) / (T * 4);
    int gemm_blocks = (n + 63) / 64;
    int agg_blocks  = (n + 15) / 16;

    // ---- CSR build ----
    k_clear   <<<nb, T>>>(n);
    k_edges   <<<eb4, T>>>(ei, E, n);
    k_off     <<<nb, T>>>(n);
    k_scatter <<<eb, T>>>(ei, E, n);

    // ---- layer 1 (+ fused BN stats) ----
    gemm64<1> <<<gemm_blocks, T>>>(x, W1, n);
    agg<1>    <<<agg_blocks, T>>>(nullptr, b1, n);

    // ---- batchnorm fold ----
    bn_final  <<<1, 64>>>(gamma, beta, n);

    // ---- layer 2 (BN+ReLU fused into GEMM input) ----
    gemm64<2> <<<gemm_blocks, T>>>(x, W2, n);
    agg<2>    <<<agg_blocks, T>>>(out, b2, n);
}

// round 6
// speedup vs baseline: 1.1307x; 1.0527x over previous
#include <cuda_runtime.h>

// ---------------- static scratch (no allocation allowed) ----------------
#define MAXN 100000
#define MAXE 1600000

__device__ __align__(16) int   g_deg [MAXN];   // in-degree incl. self-loop
__device__ __align__(16) float g_dinv[MAXN];
__device__ __align__(16) int   g_off [MAXN];   // CSR start per dst node
__device__ __align__(16) int   g_pos [MAXN];   // scatter cursor
__device__ __align__(16) int   g_csrc[MAXE];   // CSR: src per slot
__device__ int g_total;
__device__ __align__(16) float g_h1  [MAXN * 64];  // x @ W1 (unscaled)
__device__ __align__(16) float g_a1  [MAXN * 64];  // layer-1 output
__device__ __align__(16) float g_h2  [MAXN * 64];  // bn(relu(a1)) @ W2 (unscaled)
__device__ __align__(16) float g_stats[128];
__device__ __align__(16) float g_scale[64];
__device__ __align__(16) float g_shift[64];

// packed fp32x2 FMA (sm_100+)
__device__ __forceinline__ void ffma2(unsigned long long& d,
                                      unsigned long long a,
                                      unsigned long long b) {
    asm("fma.rn.f32x2 %0, %1, %2, %3;" : "=l"(d) : "l"(a), "l"(b), "l"(d));
}
__device__ __forceinline__ unsigned long long pack_dup(float a) {
    unsigned long long r;
    asm("mov.b64 %0, {%1, %1};" : "=l"(r) : "f"(a));
    return r;
}
__device__ __forceinline__ float2 unpack2(unsigned long long v) {
    float2 r;
    asm("mov.b64 {%0, %1}, %2;" : "=f"(r.x), "=f"(r.y) : "l"(v));
    return r;
}

// ---------------- prep ----------------
__global__ void k_clear(int n) {
    int i = blockIdx.x * blockDim.x + threadIdx.x;
    if (i < n) g_deg[i] = 1;
    if (blockIdx.x == 0) {
        if (threadIdx.x < 128) g_stats[threadIdx.x] = 0.f;
        if (threadIdx.x == 0)  g_total = 0;
    }
}

__global__ void k_edges(const int* __restrict__ ei, int E, int n) {
    int e4 = (blockIdx.x * blockDim.x + threadIdx.x) * 4;
    if (e4 >= E) return;
    const int* dstp = ei + E;
    if (e4 + 3 < E) {
        int4 d4 = *(const int4*)&dstp[e4];
        if ((unsigned)d4.x >= (unsigned)n) d4.x = 0;
        if ((unsigned)d4.y >= (unsigned)n) d4.y = 0;
        if ((unsigned)d4.z >= (unsigned)n) d4.z = 0;
        if ((unsigned)d4.w >= (unsigned)n) d4.w = 0;
        atomicAdd(&g_deg[d4.x], 1);
        atomicAdd(&g_deg[d4.y], 1);
        atomicAdd(&g_deg[d4.z], 1);
        atomicAdd(&g_deg[d4.w], 1);
    } else {
        for (int e = e4; e < E; e++) {
            int d = dstp[e];
            if ((unsigned)d >= (unsigned)n) d = 0;
            atomicAdd(&g_deg[d], 1);
        }
    }
}

__global__ __launch_bounds__(256) void k_off(int n) {
    __shared__ int sh[256];
    __shared__ int base;
    int tid = threadIdx.x;
    int i = blockIdx.x * 256 + tid;
    int deg = (i < n) ? g_deg[i] : 1;
    int v = deg - 1;
    sh[tid] = v;
    __syncthreads();
    #pragma unroll
    for (int o = 1; o < 256; o <<= 1) {
        int t = (tid >= o) ? sh[tid - o] : 0;
        __syncthreads();
        sh[tid] += t;
        __syncthreads();
    }
    if (tid == 255) base = atomicAdd(&g_total, sh[255]);
    __syncthreads();
    if (i < n) {
        int start = base + sh[tid] - v;
        g_off[i]  = start;
        g_pos[i]  = start;
        g_dinv[i] = rsqrtf((float)deg);
    }
}

// scatter src ids, 4 edges per thread with vector loads
__global__ void k_scatter(const int* __restrict__ ei, int E, int n) {
    int e4 = (blockIdx.x * blockDim.x + threadIdx.x) * 4;
    if (e4 >= E) return;
    if (e4 + 3 < E) {
        int4 s4 = *(const int4*)&ei[e4];
        int4 d4 = *(const int4*)&ei[E + e4];
        if ((unsigned)s4.x >= (unsigned)n) s4.x = 0;
        if ((unsigned)s4.y >= (unsigned)n) s4.y = 0;
        if ((unsigned)s4.z >= (unsigned)n) s4.z = 0;
        if ((unsigned)s4.w >= (unsigned)n) s4.w = 0;
        if ((unsigned)d4.x >= (unsigned)n) d4.x = 0;
        if ((unsigned)d4.y >= (unsigned)n) d4.y = 0;
        if ((unsigned)d4.z >= (unsigned)n) d4.z = 0;
        if ((unsigned)d4.w >= (unsigned)n) d4.w = 0;
        int p0 = atomicAdd(&g_pos[d4.x], 1);
        int p1 = atomicAdd(&g_pos[d4.y], 1);
        int p2 = atomicAdd(&g_pos[d4.z], 1);
        int p3 = atomicAdd(&g_pos[d4.w], 1);
        if (p0 < MAXE) g_csrc[p0] = s4.x;
        if (p1 < MAXE) g_csrc[p1] = s4.y;
        if (p2 < MAXE) g_csrc[p2] = s4.z;
        if (p3 < MAXE) g_csrc[p3] = s4.w;
    } else {
        for (int e = e4; e < E; e++) {
            int s = ei[e];
            int d = ei[E + e];
            if ((unsigned)s >= (unsigned)n) s = 0;
            if ((unsigned)d >= (unsigned)n) d = 0;
            int p = atomicAdd(&g_pos[d], 1);
            if (p < MAXE) g_csrc[p] = s;
        }
    }
}

// ---------------- GEMM: [n,K] @ [K,64] -> [n,64] (unscaled output) ----------------
template <int LAYER>
__global__ __launch_bounds__(256)
void gemm64(const float* __restrict__ xin, const float* __restrict__ Wm, int n) {
    constexpr int K = (LAYER == 1) ? 128 : 64;
    const float* X = (LAYER == 1) ? xin : (const float*)g_a1;
    float* H = (LAYER == 1) ? g_h1 : g_h2;

    __shared__ __align__(16) float sX[64 * 68];
    __shared__ __align__(16) float sW[64 * 64];

    int t  = threadIdx.x;
    int tx = t & 15;
    int ty = t >> 4;
    int c0 = tx * 4;
    int r0 = ty * 4;
    int rowBase = blockIdx.x * 64;

    unsigned long long acc2[4][2] = {};

    for (int k0 = 0; k0 < K; k0 += 64) {
        int kq = tx;
        int rr = ty;
        #pragma unroll
        for (int j = 0; j < 4; j++) {
            int kk = rr + j * 16;
            float4 wv = *(const float4*)&Wm[(long)(k0 + kk) * 64 + kq * 4];
            *(float4*)&sW[kk * 64 + kq * 4] = wv;
        }
        #pragma unroll
        for (int j = 0; j < 4; j++) {
            int row  = rr + j * 16;
            int grow = rowBase + row;
            float4 xv = make_float4(0.f, 0.f, 0.f, 0.f);
            if (grow < n) {
                xv = *(const float4*)&X[(long)grow * K + k0 + kq * 4];
                if (LAYER == 2) {
                    float4 sc = *(const float4*)&g_scale[kq * 4];
                    float4 sf = *(const float4*)&g_shift[kq * 4];
                    xv.x = fmaxf(fmaf(xv.x, sc.x, sf.x), 0.f);
                    xv.y = fmaxf(fmaf(xv.y, sc.y, sf.y), 0.f);
                    xv.z = fmaxf(fmaf(xv.z, sc.z, sf.z), 0.f);
                    xv.w = fmaxf(fmaf(xv.w, sc.w, sf.w), 0.f);
                }
            }
            *(float4*)&sX[row * 68 + kq * 4] = xv;
        }
        __syncthreads();

        #pragma unroll
        for (int kk = 0; kk < 64; kk++) {
            ulonglong2 wp = *(const ulonglong2*)&sW[kk * 64 + c0];
            #pragma unroll
            for (int i = 0; i < 4; i++) {
                unsigned long long aa = pack_dup(sX[(r0 + i) * 68 + kk]);
                ffma2(acc2[i][0], aa, wp.x);
                ffma2(acc2[i][1], aa, wp.y);
            }
        }
        __syncthreads();
    }

    #pragma unroll
    for (int i = 0; i < 4; i++) {
        int grow = rowBase + r0 + i;
        if (grow < n) {
            float2 lo = unpack2(acc2[i][0]);
            float2 hi = unpack2(acc2[i][1]);
            *(float4*)&H[(long)grow * 64 + c0] = make_float4(lo.x, lo.y, hi.x, hi.y);
        }
    }
}

// ---------------- aggregation ----------------
// out[i] = dinv[i] * ( dinv[i]*H[i] + sum_j dinv[s_j]*H[s_j] ) + b
template <int LAYER>
__global__ __launch_bounds__(256)
void agg(float* __restrict__ outp, const float* __restrict__ b, int n) {
    const float* H = (LAYER == 1) ? g_h1 : g_h2;
    float* O = (LAYER == 1) ? g_a1 : outp;

    int tid   = threadIdx.x;
    int local = tid >> 4;
    int q     = tid & 15;
    int i = blockIdx.x * 16 + local;
    bool valid = (i < n);

    float4 out4 = make_float4(0.f, 0.f, 0.f, 0.f);
    if (valid) {
        float di = g_dinv[i];
        float4 h = *(const float4*)&H[(long)i * 64 + q * 4];
        float4 acc = make_float4(h.x * di, h.y * di, h.z * di, h.w * di);

        int start = g_off[i];
        int end   = start + (g_deg[i] - 1);
        int j = start;
        for (; j + 3 < end; j += 4) {
            int s0 = g_csrc[j];
            int s1 = g_csrc[j + 1];
            int s2 = g_csrc[j + 2];
            int s3 = g_csrc[j + 3];
            float w0 = g_dinv[s0];
            float w1 = g_dinv[s1];
            float w2 = g_dinv[s2];
            float w3 = g_dinv[s3];
            float4 v0 = *(const float4*)&H[(long)s0 * 64 + q * 4];
            float4 v1 = *(const float4*)&H[(long)s1 * 64 + q * 4];
            float4 v2 = *(const float4*)&H[(long)s2 * 64 + q * 4];
            float4 v3 = *(const float4*)&H[(long)s3 * 64 + q * 4];
            acc.x = fmaf(w0, v0.x, acc.x); acc.y = fmaf(w0, v0.y, acc.y);
            acc.z = fmaf(w0, v0.z, acc.z); acc.w = fmaf(w0, v0.w, acc.w);
            acc.x = fmaf(w1, v1.x, acc.x); acc.y = fmaf(w1, v1.y, acc.y);
            acc.z = fmaf(w1, v1.z, acc.z); acc.w = fmaf(w1, v1.w, acc.w);
            acc.x = fmaf(w2, v2.x, acc.x); acc.y = fmaf(w2, v2.y, acc.y);
            acc.z = fmaf(w2, v2.z, acc.z); acc.w = fmaf(w2, v2.w, acc.w);
            acc.x = fmaf(w3, v3.x, acc.x); acc.y = fmaf(w3, v3.y, acc.y);
            acc.z = fmaf(w3, v3.z, acc.z); acc.w = fmaf(w3, v3.w, acc.w);
        }
        for (; j < end; j++) {
            int s0 = g_csrc[j];
            float w0 = g_dinv[s0];
            float4 v0 = *(const float4*)&H[(long)s0 * 64 + q * 4];
            acc.x = fmaf(w0, v0.x, acc.x); acc.y = fmaf(w0, v0.y, acc.y);
            acc.z = fmaf(w0, v0.z, acc.z); acc.w = fmaf(w0, v0.w, acc.w);
        }

        float4 bb = *(const float4*)&b[q * 4];
        out4.x = fmaf(acc.x, di, bb.x);
        out4.y = fmaf(acc.y, di, bb.y);
        out4.z = fmaf(acc.z, di, bb.z);
        out4.w = fmaf(acc.w, di, bb.w);

        *(float4*)&O[(long)i * 64 + q * 4] = out4;
    }

    if (LAYER == 1) {
        __shared__ __align__(16) float sv[16][68];
        *(float4*)&sv[local][q * 4] = out4;
        __syncthreads();
        if (tid < 64) {
            float s = 0.f, s2 = 0.f;
            #pragma unroll
            for (int r = 0; r < 16; r++) {
                float v = sv[r][tid];
                s  += v;
                s2 += v * v;
            }
            atomicAdd(&g_stats[tid], s);
            atomicAdd(&g_stats[64 + tid], s2);
        }
    }
}

// ---------------- batchnorm fold ----------------
__global__ void bn_final(const float* __restrict__ gamma,
                         const float* __restrict__ beta, int n) {
    int c = threadIdx.x;
    if (c >= 64) return;
    float inv_n = 1.f / (float)n;
    float mean = g_stats[c] * inv_n;
    float var  = g_stats[64 + c] * inv_n - mean * mean;
    float rs   = rsqrtf(var + 1e-5f);
    float sc   = rs * gamma[c];
    g_scale[c] = sc;
    g_shift[c] = fmaf(-mean, sc, beta[c]);
}

// ---------------- launch (2-stream fork: GEMM1 overlaps CSR build) ----------------
extern "C" void kernel_launch(void* const* d_in, const int* in_sizes, int n_in,
                              void* d_out, int out_size) {
    const float* x     = (const float*)d_in[0];
    const int*   ei    = (const int*)d_in[1];
    const float* W1    = (const float*)d_in[2];
    const float* b1    = (const float*)d_in[3];
    const float* W2    = (const float*)d_in[4];
    const float* b2    = (const float*)d_in[5];
    const float* gamma = (const float*)d_in[6];
    const float* beta  = (const float*)d_in[7];
    float*       out   = (float*)d_out;

    int n = in_sizes[0] / 128;
    int E = in_sizes[1] / 2;

    const int T = 256;
    int nb  = (n + T - 1) / T;
    int eb4 = (E + T * 4 - 1) / (T * 4);
    int gemm_blocks = (n + 63) / 64;
    int agg_blocks  = (n + 15) / 16;

    // fork stream + events (created per call; NOT destroyed — destroying a
    // forked stream/event mid-capture invalidates the graph, and kernel_launch
    // only runs a handful of times host-side)
    cudaStream_t s2;
    cudaStreamCreateWithFlags(&s2, cudaStreamNonBlocking);
    cudaEvent_t evF, evG;
    cudaEventCreateWithFlags(&evF, cudaEventDisableTiming);
    cudaEventCreateWithFlags(&evG, cudaEventDisableTiming);

    // fork: GEMM1 (independent of graph structure) on s2
    cudaEventRecord(evF, 0);
    cudaStreamWaitEvent(s2, evF, 0);
    gemm64<1> <<<gemm_blocks, T, 0, s2>>>(x, W1, n);
    cudaEventRecord(evG, s2);

    // CSR build on the capture stream
    k_clear   <<<nb, T>>>(n);
    k_edges   <<<eb4, T>>>(ei, E, n);
    k_off     <<<nb, T>>>(n);
    k_scatter <<<eb4, T>>>(ei, E, n);

    // join
    cudaStreamWaitEvent(0, evG, 0);

    // layer 1 aggregation (+ fused BN stats), BN fold, layer 2
    agg<1>    <<<agg_blocks, T>>>(nullptr, b1, n);
    bn_final  <<<1, 64>>>(gamma, beta, n);
    gemm64<2> <<<gemm_blocks, T>>>(x, W2, n);
    agg<2>    <<<agg_blocks, T>>>(out, b2, n);
}